// round 1
// baseline (speedup 1.0000x reference)
#include <cuda_runtime.h>
#include <stdint.h>

#define D       512
#define BTILE   128
#define MTILE   128
#define KSTEP   8
#define MAX_M   65536
#define MAX_B   512

// Scratch (allocation-free rule: __device__ globals)
__device__ float g_inv_norm[MAX_M];
__device__ unsigned long long g_best[MAX_B];

// Monotonic float->uint mapping: a > b (as float)  <=>  f2mono(a) > f2mono(b)
__device__ __forceinline__ unsigned int f2mono(float f) {
    unsigned int b = __float_as_uint(f);
    return (b & 0x80000000u) ? ~b : (b | 0x80000000u);
}

// One warp per memory row: inv_norm[m] = rsqrt(max(sum(mem[m]^2), 1e-12))
__global__ void norm_kernel(const float* __restrict__ mem, int M) {
    int warp = (blockIdx.x * blockDim.x + threadIdx.x) >> 5;
    int lane = threadIdx.x & 31;
    if (warp >= M) return;
    const float4* row = (const float4*)(mem + (size_t)warp * D);
    float s = 0.f;
#pragma unroll
    for (int i = 0; i < 4; i++) {
        float4 v = row[lane + 32 * i];
        s += v.x * v.x + v.y * v.y + v.z * v.z + v.w * v.w;
    }
#pragma unroll
    for (int o = 16; o > 0; o >>= 1) s += __shfl_xor_sync(0xffffffffu, s, o);
    if (lane == 0) g_inv_norm[warp] = rsqrtf(fmaxf(s, 1e-12f));
}

__global__ void init_best_kernel(int B) {
    int b = blockIdx.x * blockDim.x + threadIdx.x;
    if (b < B) g_best[b] = 0ull;  // smallest possible key
}

// Fused GEMM (dot products) + per-query running argmax.
// Tile: 128 b x 128 m, 256 threads, 8x8 per thread, K chunks of 8.
__global__ __launch_bounds__(256) void gemm_argmax_kernel(
    const float* __restrict__ ctx, const float* __restrict__ mem, int B, int M)
{
    __shared__ float As[KSTEP][BTILE];
    __shared__ float Bs[KSTEP][MTILE];

    const int tid = threadIdx.x;
    const int tx = tid & 15;   // m group (0..15)
    const int ty = tid >> 4;   // b group (0..15)
    const int b0 = blockIdx.y * BTILE;
    const int m0 = blockIdx.x * MTILE;

    float acc[8][8];
#pragma unroll
    for (int i = 0; i < 8; i++)
#pragma unroll
        for (int j = 0; j < 8; j++) acc[i][j] = 0.f;

    // Global->shared loader mapping: 256 threads load 128 rows x 8 k (2 float4 per row)
    const int lrow = tid >> 1;          // 0..127
    const int lcg  = (tid & 1) * 4;     // 0 or 4
    const float* aptr = ctx + (size_t)(b0 + lrow) * D + lcg;
    const float* bptr = mem + (size_t)(m0 + lrow) * D + lcg;

    for (int k0 = 0; k0 < D; k0 += KSTEP) {
        float4 av = *(const float4*)(aptr + k0);
        float4 bv = *(const float4*)(bptr + k0);
        __syncthreads();   // previous iteration consumers done
        As[lcg + 0][lrow] = av.x; As[lcg + 1][lrow] = av.y;
        As[lcg + 2][lrow] = av.z; As[lcg + 3][lrow] = av.w;
        Bs[lcg + 0][lrow] = bv.x; Bs[lcg + 1][lrow] = bv.y;
        Bs[lcg + 2][lrow] = bv.z; Bs[lcg + 3][lrow] = bv.w;
        __syncthreads();
#pragma unroll
        for (int kk = 0; kk < KSTEP; kk++) {
            float a[8], b[8];
#pragma unroll
            for (int i = 0; i < 8; i++) a[i] = As[kk][ty * 8 + i];
#pragma unroll
            for (int j = 0; j < 8; j++) b[j] = Bs[kk][tx * 8 + j];
#pragma unroll
            for (int i = 0; i < 8; i++)
#pragma unroll
                for (int j = 0; j < 8; j++)
                    acc[i][j] = fmaf(a[i], b[j], acc[i][j]);
        }
    }

    // Epilogue: score = dot * inv_norm[m]  (context norm skipped: positive
    // per-row scale cannot change argmax). Track per-thread best over 8 m's,
    // reduce across the 16 tx lanes (half-warp), then one atomicMax per b-row.
    float invn[8];
#pragma unroll
    for (int j = 0; j < 8; j++) invn[j] = g_inv_norm[m0 + tx * 8 + j];

#pragma unroll
    for (int i = 0; i < 8; i++) {
        float bestv = -3.4e38f;
        int bestm = m0 + tx * 8;
#pragma unroll
        for (int j = 0; j < 8; j++) {
            float s = acc[i][j] * invn[j];
            if (s > bestv) { bestv = s; bestm = m0 + tx * 8 + j; }
        }
        // key: high 32 = monotone score, low 32 = ~index so ties pick SMALLEST m
        unsigned long long key =
            ((unsigned long long)f2mono(bestv) << 32) |
            (unsigned long long)(0xFFFFFFFFu - (unsigned)bestm);
#pragma unroll
        for (int o = 8; o > 0; o >>= 1) {
            unsigned long long other = __shfl_xor_sync(0xffffffffu, key, o, 16);
            if (other > key) key = other;
        }
        if (tx == 0) atomicMax(&g_best[b0 + ty * 8 + i], key);
    }
}

// out[0, b, :] = memory[best[b], :]
__global__ void gather_kernel(const float* __restrict__ mem, float* __restrict__ out) {
    int b = blockIdx.x;
    unsigned idx = 0xFFFFFFFFu - (unsigned)(g_best[b] & 0xFFFFFFFFull);
    const float4* src = (const float4*)(mem + (size_t)idx * D);
    float4* dst = (float4*)(out + (size_t)b * D);
    for (int i = threadIdx.x; i < D / 4; i += blockDim.x) dst[i] = src[i];
}

extern "C" void kernel_launch(void* const* d_in, const int* in_sizes, int n_in,
                              void* d_out, int out_size)
{
    const float* ctx = (const float*)d_in[0];   // [B, D] f32
    const float* mem = (const float*)d_in[1];   // [M, D] f32
    float* out = (float*)d_out;                 // [1, B, D] f32

    const int B = in_sizes[0] / D;  // 512
    const int M = in_sizes[1] / D;  // 65536

    // 1) memory row inverse norms (one warp per row)
    norm_kernel<<<(M * 32 + 255) / 256, 256>>>(mem, M);
    // 2) reset argmax table (must happen every launch: deterministic replays)
    init_best_kernel<<<(B + 255) / 256, 256>>>(B);
    // 3) fused similarity + argmax
    dim3 grid(M / MTILE, B / BTILE);
    gemm_argmax_kernel<<<grid, 256>>>(ctx, mem, B, M);
    // 4) gather winning rows
    gather_kernel<<<B, 128>>>(mem, out);
}

// round 5
// speedup vs baseline: 2.1849x; 2.1849x over previous
#include <cuda_runtime.h>
#include <cuda_bf16.h>
#include <stdint.h>

#define D       512
#define NB      512
#define NM      65536
#define BT      128
#define MT      128
#define KT      32                 // k per pipeline stage (bf16 elems)
#define NSTG    (D / KT)           // 16
#define ROWB    80                 // padded smem row stride (bytes) -> conflict-free
#define ABYTES  (128 * ROWB)       // 10240 per tile array
#define NTILES  (NM / MT)          // 512
#define DELTA   0.09f

// ---------------- device scratch (allocation-free rule) ----------------
__device__ __nv_bfloat16 g_mem_b[NM * D];   // normalized memory, bf16 row-major
__device__ __nv_bfloat16 g_ctx_b[NB * D];   // context, bf16 row-major
__device__ float g_inv_norm[NM];
__device__ float g_tilebest[NB * NTILES];
__device__ int   g_bestidx[NB];

// ---------------- helpers ----------------
__device__ __forceinline__ unsigned int f2mono(float f) {
    unsigned int b = __float_as_uint(f);
    return (b & 0x80000000u) ? ~b : (b | 0x80000000u);
}
__device__ __forceinline__ uint32_t s2u(const void* p) {
    return (uint32_t)__cvta_generic_to_shared(p);
}
__device__ __forceinline__ void cp16(uint32_t dst, const void* src) {
    asm volatile("cp.async.cg.shared.global [%0], [%1], 16;" :: "r"(dst), "l"(src));
}
__device__ __forceinline__ void ldm_x4(uint32_t& r0, uint32_t& r1, uint32_t& r2, uint32_t& r3, uint32_t a) {
    asm volatile("ldmatrix.sync.aligned.m8n8.x4.shared.b16 {%0,%1,%2,%3}, [%4];"
                 : "=r"(r0), "=r"(r1), "=r"(r2), "=r"(r3) : "r"(a));
}
__device__ __forceinline__ void mma16816(float* c, const uint32_t* a, const uint32_t* b) {
    asm volatile("mma.sync.aligned.m16n8k16.row.col.f32.bf16.bf16.f32 "
                 "{%0,%1,%2,%3}, {%4,%5,%6,%7}, {%8,%9}, {%0,%1,%2,%3};"
                 : "+f"(c[0]), "+f"(c[1]), "+f"(c[2]), "+f"(c[3])
                 : "r"(a[0]), "r"(a[1]), "r"(a[2]), "r"(a[3]), "r"(b[0]), "r"(b[1]));
}

// ---------------- 1) convert fp32 -> bf16 (memory rows normalized) ----------------
__global__ __launch_bounds__(256) void convert_kernel(const float* __restrict__ src, int rows, int is_mem) {
    int row = blockIdx.x * 8 + (threadIdx.x >> 5);
    int lane = threadIdx.x & 31;
    if (row >= rows) return;
    const float4* rp = (const float4*)(src + (size_t)row * D);
    float4 v[4];
    float ssq = 0.f;
#pragma unroll
    for (int i = 0; i < 4; i++) {
        v[i] = rp[lane * 4 + i];
        ssq += v[i].x * v[i].x + v[i].y * v[i].y + v[i].z * v[i].z + v[i].w * v[i].w;
    }
    float invn = 1.0f;
    if (is_mem) {
#pragma unroll
        for (int o = 16; o > 0; o >>= 1) ssq += __shfl_xor_sync(0xffffffffu, ssq, o);
        invn = rsqrtf(fmaxf(ssq, 1e-12f));
        if (lane == 0) g_inv_norm[row] = invn;
    }
    unsigned short h[16];
    const float* vs = (const float*)v;
#pragma unroll
    for (int i = 0; i < 16; i++)
        h[i] = __bfloat16_as_ushort(__float2bfloat16_rn(vs[i] * invn));
    __nv_bfloat16* dst = (is_mem ? g_mem_b : g_ctx_b) + (size_t)row * D + lane * 16;
#pragma unroll
    for (int g = 0; g < 2; g++) {
        uint4 w;
        w.x = ((uint32_t)h[g * 8 + 1] << 16) | h[g * 8 + 0];
        w.y = ((uint32_t)h[g * 8 + 3] << 16) | h[g * 8 + 2];
        w.z = ((uint32_t)h[g * 8 + 5] << 16) | h[g * 8 + 4];
        w.w = ((uint32_t)h[g * 8 + 7] << 16) | h[g * 8 + 6];
        *(uint4*)(dst + g * 8) = w;
    }
}

// ---------------- 2) HMMA GEMM + per-(b, m-tile) max ----------------
// grid: (NTILES=512 m [fastest], 4 b). 256 threads = 8 warps, warp = 64b x 32m.
__global__ __launch_bounds__(256) void gemm_kernel() {
    __shared__ __align__(128) char sm[2 * 2 * ABYTES];   // [stage][A|B]
    __shared__ float smaxw[4][128];

    const int tid = threadIdx.x, lane = tid & 31, w = tid >> 5;
    const int wb = w >> 2, wm = w & 3;           // warp b-half, warp m-quarter
    const int mtile = blockIdx.x;
    const int b0 = blockIdx.y * BT;

    // global load mapping: thread -> (row tid>>1, 32B half (tid&1))
    const int arow = tid >> 1;
    const int ac = (tid & 1) * 32;               // byte offset within 64B stage-row
    const char* asrc = (const char*)(g_ctx_b + (size_t)(b0 + arow) * D) + ac;
    const char* bsrc = (const char*)(g_mem_b + (size_t)(mtile * MT + arow) * D) + ac;
    const uint32_t smbase = s2u(sm);
    const uint32_t adst = smbase + arow * ROWB + ac;
    const uint32_t bdst = adst + ABYTES;

    float acc[4][4][4];
#pragma unroll
    for (int i = 0; i < 4; i++)
#pragma unroll
        for (int j = 0; j < 4; j++)
#pragma unroll
            for (int k = 0; k < 4; k++) acc[i][j][k] = 0.f;

    // ldmatrix source addresses (per stage-buffer base)
    const uint32_t aoff = (uint32_t)((wb * 64 + (lane & 15)) * ROWB + (lane >> 4) * 16);
    const uint32_t boff = (uint32_t)(ABYTES + (wm * 32 + (lane >> 4) * 8 + (lane & 7)) * ROWB + ((lane >> 3) & 1) * 16);

    auto load_stage = [&](int s) {
        uint32_t off = (uint32_t)((s & 1) * (2 * ABYTES));
        const char* a = asrc + s * 64;
        const char* b = bsrc + s * 64;
        cp16(adst + off, a); cp16(adst + off + 16, a + 16);
        cp16(bdst + off, b); cp16(bdst + off + 16, b + 16);
    };

    load_stage(0);
    asm volatile("cp.async.commit_group;" ::: "memory");

    for (int s = 0; s < NSTG; s++) {
        if (s + 1 < NSTG) {
            load_stage(s + 1);
            asm volatile("cp.async.commit_group;" ::: "memory");
            asm volatile("cp.async.wait_group 1;" ::: "memory");
        } else {
            asm volatile("cp.async.wait_group 0;" ::: "memory");
        }
        __syncthreads();

        uint32_t sb = smbase + (uint32_t)((s & 1) * (2 * ABYTES));
#pragma unroll
        for (int h = 0; h < 2; h++) {            // two k16 halves of the k32 stage
            uint32_t afr[4][4], bfr[2][4];
#pragma unroll
            for (int i = 0; i < 4; i++)
                ldm_x4(afr[i][0], afr[i][1], afr[i][2], afr[i][3],
                       sb + aoff + (uint32_t)(i * 16 * ROWB + h * 32));
#pragma unroll
            for (int p = 0; p < 2; p++)
                ldm_x4(bfr[p][0], bfr[p][1], bfr[p][2], bfr[p][3],
                       sb + boff + (uint32_t)(p * 16 * ROWB + h * 32));
#pragma unroll
            for (int i = 0; i < 4; i++)
#pragma unroll
                for (int j = 0; j < 4; j++)
                    mma16816(acc[i][j], afr[i], &bfr[j >> 1][(j & 1) * 2]);
        }
        __syncthreads();
    }

    // epilogue: per-thread row maxes -> quad shfl -> smem -> per-tile max
#pragma unroll
    for (int i = 0; i < 4; i++) {
        float vlo = -3.4e38f, vhi = -3.4e38f;
#pragma unroll
        for (int j = 0; j < 4; j++) {
            vlo = fmaxf(vlo, fmaxf(acc[i][j][0], acc[i][j][1]));
            vhi = fmaxf(vhi, fmaxf(acc[i][j][2], acc[i][j][3]));
        }
        vlo = fmaxf(vlo, __shfl_xor_sync(0xffffffffu, vlo, 1));
        vlo = fmaxf(vlo, __shfl_xor_sync(0xffffffffu, vlo, 2));
        vhi = fmaxf(vhi, __shfl_xor_sync(0xffffffffu, vhi, 1));
        vhi = fmaxf(vhi, __shfl_xor_sync(0xffffffffu, vhi, 2));
        if ((lane & 3) == 0) {
            int r = wb * 64 + i * 16 + (lane >> 2);
            smaxw[wm][r] = vlo;
            smaxw[wm][r + 8] = vhi;
        }
    }
    __syncthreads();
    if (tid < 128) {
        float v = fmaxf(fmaxf(smaxw[0][tid], smaxw[1][tid]),
                        fmaxf(smaxw[2][tid], smaxw[3][tid]));
        g_tilebest[(size_t)(b0 + tid) * NTILES + mtile] = v;
    }
}

// ---------------- 3) rescue: exact fp32 rescore of candidate tiles ----------------
__global__ __launch_bounds__(256) void rescue_kernel(const float* __restrict__ ctx,
                                                     const float* __restrict__ mem) {
    __shared__ __align__(16) float cs[D];
    __shared__ float tb[NTILES];
    __shared__ float sred[8];
    __shared__ unsigned long long skey[8];
    int b = blockIdx.x, tid = threadIdx.x, wid = tid >> 5, lane = tid & 31;

    cs[tid] = ctx[(size_t)b * D + tid];
    cs[tid + 256] = ctx[(size_t)b * D + tid + 256];
    tb[tid] = g_tilebest[(size_t)b * NTILES + tid];
    tb[tid + 256] = g_tilebest[(size_t)b * NTILES + tid + 256];
    __syncthreads();

    float v = fmaxf(tb[tid], tb[tid + 256]);
#pragma unroll
    for (int o = 16; o > 0; o >>= 1) v = fmaxf(v, __shfl_xor_sync(0xffffffffu, v, o));
    if (lane == 0) sred[wid] = v;
    __syncthreads();
    if (tid == 0) {
        float m = sred[0];
#pragma unroll
        for (int i = 1; i < 8; i++) m = fmaxf(m, sred[i]);
        sred[0] = m;
    }
    __syncthreads();
    const float thresh = sred[0] - DELTA;

    unsigned long long bestkey = 0ull;
    for (int t = 0; t < NTILES / 2; t++) {       // 256-wide candidate groups
        if (fmaxf(tb[2 * t], tb[2 * t + 1]) < thresh) continue;
        int m = t * 256 + tid;
        const float4* mr = (const float4*)(mem + (size_t)m * D);
        float s = 0.f;
#pragma unroll 8
        for (int i = 0; i < D / 4; i++) {
            float4 q = mr[i];
            float4 c = *(const float4*)&cs[i * 4];
            s = fmaf(q.x, c.x, s); s = fmaf(q.y, c.y, s);
            s = fmaf(q.z, c.z, s); s = fmaf(q.w, c.w, s);
        }
        s *= g_inv_norm[m];
        unsigned long long key = ((unsigned long long)f2mono(s) << 32) |
                                 (unsigned long long)(0xFFFFFFFFu - (unsigned)m);
        if (key > bestkey) bestkey = key;
    }
#pragma unroll
    for (int o = 16; o > 0; o >>= 1) {
        unsigned long long ok = __shfl_xor_sync(0xffffffffu, bestkey, o);
        if (ok > bestkey) bestkey = ok;
    }
    if (lane == 0) skey[wid] = bestkey;
    __syncthreads();
    if (tid == 0) {
        unsigned long long k = skey[0];
#pragma unroll
        for (int i = 1; i < 8; i++) if (skey[i] > k) k = skey[i];
        g_bestidx[b] = (int)(0xFFFFFFFFu - (unsigned)(k & 0xFFFFFFFFull));
    }
}

// ---------------- 4) gather ----------------
__global__ void gather_kernel(const float* __restrict__ mem, float* __restrict__ out) {
    int b = blockIdx.x;
    int idx = g_bestidx[b];
    const float4* src = (const float4*)(mem + (size_t)idx * D);
    float4* dst = (float4*)(out + (size_t)b * D);
    for (int i = threadIdx.x; i < D / 4; i += blockDim.x) dst[i] = src[i];
}

// ---------------- launch ----------------
extern "C" void kernel_launch(void* const* d_in, const int* in_sizes, int n_in,
                              void* d_out, int out_size)
{
    const float* ctx = (const float*)d_in[0];   // [512, 512] f32
    const float* mem = (const float*)d_in[1];   // [65536, 512] f32
    float* out = (float*)d_out;                 // [1, 512, 512] f32

    convert_kernel<<<NM / 8, 256>>>(mem, NM, 1);
    convert_kernel<<<NB / 8, 256>>>(ctx, NB, 0);
    gemm_kernel<<<dim3(NTILES, NB / BT), 256>>>();
    rescue_kernel<<<NB, 256>>>(ctx, mem);
    gather_kernel<<<NB, 128>>>(mem, out);
}

// round 6
// speedup vs baseline: 4.5294x; 2.0731x over previous
#include <cuda_runtime.h>
#include <cuda_bf16.h>
#include <stdint.h>

#define D       512
#define NB      512
#define NM      65536
#define BT      128
#define MT      128
#define KT      32                 // k per pipeline stage (bf16 elems)
#define NSTG    (D / KT)           // 16
#define ROWB    80                 // padded smem row stride (bytes) -> conflict-free
#define ABYTES  (128 * ROWB)       // 10240 per tile array
#define STGB    (2 * ABYTES)       // 20480 per stage (A+B)
#define NBUF    4
#define SMEM_DYN (NBUF * STGB)     // 81920
#define NTILES  (NM / MT)          // 512
#define NGRP    (NM / 8)           // 8192 8-row groups
#define DELTA   0.09f

// ---------------- device scratch (allocation-free rule) ----------------
__device__ __nv_bfloat16 g_mem_b[NM * D];   // normalized memory, bf16 row-major
__device__ __nv_bfloat16 g_ctx_b[NB * D];   // context, bf16 row-major
__device__ float g_inv_norm[NM];
__device__ float g_subbest[NB * NGRP];      // per (query, 8-row m-group) bf16 score max
__device__ int   g_bestidx[NB];

// ---------------- helpers ----------------
__device__ __forceinline__ unsigned int f2mono(float f) {
    unsigned int b = __float_as_uint(f);
    return (b & 0x80000000u) ? ~b : (b | 0x80000000u);
}
__device__ __forceinline__ uint32_t s2u(const void* p) {
    return (uint32_t)__cvta_generic_to_shared(p);
}
__device__ __forceinline__ void cp16(uint32_t dst, const void* src) {
    asm volatile("cp.async.cg.shared.global [%0], [%1], 16;" :: "r"(dst), "l"(src));
}
__device__ __forceinline__ void ldm_x4(uint32_t& r0, uint32_t& r1, uint32_t& r2, uint32_t& r3, uint32_t a) {
    asm volatile("ldmatrix.sync.aligned.m8n8.x4.shared.b16 {%0,%1,%2,%3}, [%4];"
                 : "=r"(r0), "=r"(r1), "=r"(r2), "=r"(r3) : "r"(a));
}
__device__ __forceinline__ void mma16816(float* c, const uint32_t* a, const uint32_t* b) {
    asm volatile("mma.sync.aligned.m16n8k16.row.col.f32.bf16.bf16.f32 "
                 "{%0,%1,%2,%3}, {%4,%5,%6,%7}, {%8,%9}, {%0,%1,%2,%3};"
                 : "+f"(c[0]), "+f"(c[1]), "+f"(c[2]), "+f"(c[3])
                 : "r"(a[0]), "r"(a[1]), "r"(a[2]), "r"(a[3]), "r"(b[0]), "r"(b[1]));
}

// ---------------- 1) convert fp32 -> bf16 (memory rows normalized) ----------------
__global__ __launch_bounds__(256) void convert_kernel(const float* __restrict__ src, int rows, int is_mem) {
    int row = blockIdx.x * 8 + (threadIdx.x >> 5);
    int lane = threadIdx.x & 31;
    if (row >= rows) return;
    const float4* rp = (const float4*)(src + (size_t)row * D);
    float4 v[4];
    float ssq = 0.f;
#pragma unroll
    for (int i = 0; i < 4; i++) {
        v[i] = rp[lane * 4 + i];
        ssq += v[i].x * v[i].x + v[i].y * v[i].y + v[i].z * v[i].z + v[i].w * v[i].w;
    }
    float invn = 1.0f;
    if (is_mem) {
#pragma unroll
        for (int o = 16; o > 0; o >>= 1) ssq += __shfl_xor_sync(0xffffffffu, ssq, o);
        invn = rsqrtf(fmaxf(ssq, 1e-12f));
        if (lane == 0) g_inv_norm[row] = invn;
    }
    unsigned short h[16];
    const float* vs = (const float*)v;
#pragma unroll
    for (int i = 0; i < 16; i++)
        h[i] = __bfloat16_as_ushort(__float2bfloat16_rn(vs[i] * invn));
    __nv_bfloat16* dst = (is_mem ? g_mem_b : g_ctx_b) + (size_t)row * D + lane * 16;
#pragma unroll
    for (int g = 0; g < 2; g++) {
        uint4 w;
        w.x = ((uint32_t)h[g * 8 + 1] << 16) | h[g * 8 + 0];
        w.y = ((uint32_t)h[g * 8 + 3] << 16) | h[g * 8 + 2];
        w.z = ((uint32_t)h[g * 8 + 5] << 16) | h[g * 8 + 4];
        w.w = ((uint32_t)h[g * 8 + 7] << 16) | h[g * 8 + 6];
        *(uint4*)(dst + g * 8) = w;
    }
}

// ---------------- 2) HMMA GEMM + per-(query, 8-m-group) max ----------------
// grid: (512 m-tiles [fastest], 4 b-tiles). 256 threads = 8 warps, warp = 64b x 32m.
// 4-stage cp.async pipeline, one __syncthreads per stage.
__global__ __launch_bounds__(256) void gemm_kernel() {
    extern __shared__ __align__(128) char dsm[];

    const int tid = threadIdx.x, lane = tid & 31, w = tid >> 5;
    const int wb = w >> 2, wm = w & 3;           // warp b-half, warp m-quarter
    const int mtile = blockIdx.x;
    const int b0 = blockIdx.y * BT;

    const int arow = tid >> 1;
    const int ac = (tid & 1) * 32;
    const char* asrc = (const char*)(g_ctx_b + (size_t)(b0 + arow) * D) + ac;
    const char* bsrc = (const char*)(g_mem_b + (size_t)(mtile * MT + arow) * D) + ac;
    const uint32_t smbase = s2u(dsm);
    const uint32_t adst = smbase + arow * ROWB + ac;

    float acc[4][4][4];
#pragma unroll
    for (int i = 0; i < 4; i++)
#pragma unroll
        for (int j = 0; j < 4; j++)
#pragma unroll
            for (int k = 0; k < 4; k++) acc[i][j][k] = 0.f;

    const uint32_t aoff = (uint32_t)((wb * 64 + (lane & 15)) * ROWB + (lane >> 4) * 16);
    const uint32_t boff = (uint32_t)(ABYTES + (wm * 32 + (lane >> 4) * 8 + (lane & 7)) * ROWB + ((lane >> 3) & 1) * 16);

    auto load_stage = [&](int s) {
        uint32_t off = (uint32_t)((s & (NBUF - 1)) * STGB);
        const char* a = asrc + s * 64;
        const char* b = bsrc + s * 64;
        cp16(adst + off, a);              cp16(adst + off + 16, a + 16);
        cp16(adst + off + ABYTES, b);     cp16(adst + off + ABYTES + 16, b + 16);
        asm volatile("cp.async.commit_group;" ::: "memory");
    };

    load_stage(0); load_stage(1); load_stage(2);

    for (int s = 0; s < NSTG; s++) {
        if (s < NSTG - 2)      asm volatile("cp.async.wait_group 2;" ::: "memory");
        else if (s == NSTG - 2) asm volatile("cp.async.wait_group 1;" ::: "memory");
        else                   asm volatile("cp.async.wait_group 0;" ::: "memory");
        __syncthreads();
        if (s + 3 < NSTG) load_stage(s + 3);

        uint32_t sb = smbase + (uint32_t)((s & (NBUF - 1)) * STGB);
#pragma unroll
        for (int h = 0; h < 2; h++) {
            uint32_t afr[4][4], bfr[2][4];
#pragma unroll
            for (int i = 0; i < 4; i++)
                ldm_x4(afr[i][0], afr[i][1], afr[i][2], afr[i][3],
                       sb + aoff + (uint32_t)(i * 16 * ROWB + h * 32));
#pragma unroll
            for (int p = 0; p < 2; p++)
                ldm_x4(bfr[p][0], bfr[p][1], bfr[p][2], bfr[p][3],
                       sb + boff + (uint32_t)(p * 16 * ROWB + h * 32));
#pragma unroll
            for (int i = 0; i < 4; i++)
#pragma unroll
                for (int j = 0; j < 4; j++)
                    mma16816(acc[i][j], afr[i], &bfr[j >> 1][(j & 1) * 2]);
        }
    }

    // epilogue: per-(query row, 8-col mma group) max.
    // acc[i][j]: c0,c1 = (row wb*64+i*16+(lane>>2), cols 2*(lane&3),+1 of group wm*4+j)
    //            c2,c3 = same cols, row +8.
    float (*sg)[16] = (float(*)[16])dsm;   // 128 x 16 staging (reuses buf0; safe: see syncs)
#pragma unroll
    for (int i = 0; i < 4; i++)
#pragma unroll
        for (int j = 0; j < 4; j++) {
            float p0 = fmaxf(acc[i][j][0], acc[i][j][1]);
            float p1 = fmaxf(acc[i][j][2], acc[i][j][3]);
            p0 = fmaxf(p0, __shfl_xor_sync(0xffffffffu, p0, 1));
            p0 = fmaxf(p0, __shfl_xor_sync(0xffffffffu, p0, 2));
            p1 = fmaxf(p1, __shfl_xor_sync(0xffffffffu, p1, 1));
            p1 = fmaxf(p1, __shfl_xor_sync(0xffffffffu, p1, 2));
            if ((lane & 3) == 0) {
                int r = wb * 64 + i * 16 + (lane >> 2);
                sg[r][wm * 4 + j] = p0;
                sg[r + 8][wm * 4 + j] = p1;
            }
        }
    __syncthreads();
    {   // thread t writes row t>>1, half t&1 (8 floats = 2 float4, 32B contiguous)
        int r = tid >> 1, half = tid & 1;
        float* dst = &g_subbest[(size_t)(b0 + r) * NGRP + mtile * 16 + half * 8];
        const float* src = &sg[r][half * 8];
        *(float4*)dst = *(const float4*)src;
        *(float4*)(dst + 4) = *(const float4*)(src + 4);
    }
}

// ---------------- 3) rescue: exact fp32 rescore of candidate 8-row groups ----------------
__global__ __launch_bounds__(256) void rescue_kernel(const float* __restrict__ ctx,
                                                     const float* __restrict__ mem) {
    __shared__ __align__(16) float sb[NGRP];     // 32 KB
    __shared__ __align__(16) float cs[D];
    __shared__ float sred[8];
    __shared__ float sthresh;
    __shared__ int clist[1024];
    __shared__ int ccount;
    __shared__ unsigned long long wkey[8];

    const int b = blockIdx.x, tid = threadIdx.x, wid = tid >> 5, lane = tid & 31;

    cs[tid] = ctx[(size_t)b * D + tid];
    cs[tid + 256] = ctx[(size_t)b * D + tid + 256];
    if (tid == 0) ccount = 0;

    // coalesced load of the 8192 group maxes + running max
    float vmax = -3.4e38f;
    const float4* gsrc = (const float4*)&g_subbest[(size_t)b * NGRP];
#pragma unroll
    for (int i = 0; i < NGRP / 4 / 256; i++) {   // 8 iters
        float4 v = gsrc[tid + i * 256];
        *(float4*)&sb[(tid + i * 256) * 4] = v;
        vmax = fmaxf(vmax, fmaxf(fmaxf(v.x, v.y), fmaxf(v.z, v.w)));
    }
#pragma unroll
    for (int o = 16; o > 0; o >>= 1) vmax = fmaxf(vmax, __shfl_xor_sync(0xffffffffu, vmax, o));
    if (lane == 0) sred[wid] = vmax;
    __syncthreads();
    if (tid == 0) {
        float m = sred[0];
#pragma unroll
        for (int i = 1; i < 8; i++) m = fmaxf(m, sred[i]);
        sthresh = m - DELTA;
    }
    __syncthreads();
    const float thresh = sthresh;

    // collect candidate groups
    for (int g = tid; g < NGRP; g += 256) {
        if (sb[g] >= thresh) {
            int pos = atomicAdd(&ccount, 1);
            if (pos < 1024) clist[pos] = g;
        }
    }
    __syncthreads();
    int nc = ccount; if (nc > 1024) nc = 1024;

    // one warp per candidate group; exact fp32 rescore of its 8 rows
    unsigned long long best = 0ull;
    for (int ci = wid; ci < nc; ci += 8) {
        int g = clist[ci];
#pragma unroll
        for (int r = 0; r < 8; r++) {
            int m = g * 8 + r;
            const float4* mr = (const float4*)(mem + (size_t)m * D);
            float s = 0.f;
#pragma unroll
            for (int i = 0; i < 4; i++) {      // lane covers cols lane*4 + i*128
                float4 q = mr[lane + i * 32];
                float4 c = *(const float4*)&cs[(lane + i * 32) * 4];
                s = fmaf(q.x, c.x, s); s = fmaf(q.y, c.y, s);
                s = fmaf(q.z, c.z, s); s = fmaf(q.w, c.w, s);
            }
#pragma unroll
            for (int o = 16; o > 0; o >>= 1) s += __shfl_xor_sync(0xffffffffu, s, o);
            s *= g_inv_norm[m];
            unsigned long long key = ((unsigned long long)f2mono(s) << 32) |
                                     (unsigned long long)(0xFFFFFFFFu - (unsigned)m);
            if (key > best) best = key;
        }
    }
#pragma unroll
    for (int o = 16; o > 0; o >>= 1) {
        unsigned long long ok = __shfl_xor_sync(0xffffffffu, best, o);
        if (ok > best) best = ok;
    }
    if (lane == 0) wkey[wid] = best;
    __syncthreads();
    if (tid == 0) {
        unsigned long long k = wkey[0];
#pragma unroll
        for (int i = 1; i < 8; i++) if (wkey[i] > k) k = wkey[i];
        g_bestidx[b] = (int)(0xFFFFFFFFu - (unsigned)(k & 0xFFFFFFFFull));
    }
}

// ---------------- 4) gather ----------------
__global__ void gather_kernel(const float* __restrict__ mem, float* __restrict__ out) {
    int b = blockIdx.x;
    int idx = g_bestidx[b];
    const float4* src = (const float4*)(mem + (size_t)idx * D);
    float4* dst = (float4*)(out + (size_t)b * D);
    for (int i = threadIdx.x; i < D / 4; i += blockDim.x) dst[i] = src[i];
}

// ---------------- launch ----------------
extern "C" void kernel_launch(void* const* d_in, const int* in_sizes, int n_in,
                              void* d_out, int out_size)
{
    const float* ctx = (const float*)d_in[0];   // [512, 512] f32
    const float* mem = (const float*)d_in[1];   // [65536, 512] f32
    float* out = (float*)d_out;                 // [1, 512, 512] f32

    static int configured = 0;
    cudaFuncSetAttribute(gemm_kernel, cudaFuncAttributeMaxDynamicSharedMemorySize, SMEM_DYN);
    (void)configured;

    convert_kernel<<<NM / 8, 256>>>(mem, NM, 1);
    convert_kernel<<<NB / 8, 256>>>(ctx, NB, 0);
    gemm_kernel<<<dim3(NTILES, NB / BT), 256, SMEM_DYN>>>();
    rescue_kernel<<<NB, 256>>>(ctx, mem);
    gather_kernel<<<NB, 128>>>(mem, out);
}